// round 11
// baseline (speedup 1.0000x reference)
#include <cuda_runtime.h>
#include <cuda_bf16.h>
#include <math.h>

#define EDIM 8192      // N == E == 8192
#define TM   128       // rows per CTA
#define TK   64        // K-chunk
#define NTH  256
#define NCHUNK (EDIM / TK)

// ---- shared memory layout (bytes) ----
#define OFF_P    65536      // 2 x (Ph 16KB + Pl 16KB) = 64 KB
#define OFF_X    131072     // 4 x 16 KB (Xh 8KB + Xl 8KB) [64 d][64 k] bf16
#define OFF_BV   196608     // 2 x 1 KB packed col triples float4[64]
#define OFF_ZC   198656     // 1 KB z[128], cnt[128]
#define OFF_W    199680     // 16 KB weight matrix (persistent)
#define SMEM_BYTES 216064
// epilogue reuse of dead region below OFF_P
#define OFF_M    0
#define MSTRIDE  65

// named barrier ids
#define BFULL0 1
#define BFULL1 2
#define BFREE0 3
#define BFREE1 4
#define BPROD  5

// ---- device scratch ----
__device__ __align__(16) float g_rA  [2][EDIM];
__device__ __align__(16) float g_rEA [2][EDIM];
__device__ __align__(16) float g_rEA2[2][EDIM];
__device__ __align__(16) float4 g_cPack[2 * EDIM];          // {b, eb, eb2, 0}
__device__ __align__(16) __nv_bfloat16 g_XhT[2][64 * EDIM]; // X^T hi split [d][k]
__device__ __align__(16) __nv_bfloat16 g_XlT[2][64 * EDIM]; // X^T lo split

// ---- PTX helpers ----
__device__ __forceinline__ unsigned smem_u32(const void* p) {
  unsigned a;
  asm("{ .reg .u64 t; cvta.to.shared.u64 t, %1; cvt.u32.u64 %0, t; }" : "=r"(a) : "l"(p));
  return a;
}
__device__ __forceinline__ void cp16(void* dst, const void* src) {
  unsigned sa = smem_u32(dst);
  asm volatile("cp.async.cg.shared.global [%0], [%1], 16;" :: "r"(sa), "l"(src) : "memory");
}
__device__ __forceinline__ void cp_commit() { asm volatile("cp.async.commit_group;" ::: "memory"); }
__device__ __forceinline__ void cp_wait1()  { asm volatile("cp.async.wait_group 1;" ::: "memory"); }

__device__ __forceinline__ void bar_sync(int id, int cnt) {
  asm volatile("bar.sync %0, %1;" :: "r"(id), "r"(cnt) : "memory");
}
__device__ __forceinline__ void bar_arrive(int id, int cnt) {
  asm volatile("bar.arrive %0, %1;" :: "r"(id), "r"(cnt) : "memory");
}

__device__ __forceinline__ void ldsm4(unsigned& r0, unsigned& r1, unsigned& r2, unsigned& r3,
                                      unsigned addr) {
  asm volatile("ldmatrix.sync.aligned.m8n8.x4.shared.b16 {%0,%1,%2,%3}, [%4];"
               : "=r"(r0), "=r"(r1), "=r"(r2), "=r"(r3) : "r"(addr));
}
__device__ __forceinline__ void mma16816(float* c, const unsigned* a, unsigned b0, unsigned b1) {
  asm volatile("mma.sync.aligned.m16n8k16.row.col.f32.bf16.bf16.f32 "
               "{%0,%1,%2,%3}, {%4,%5,%6,%7}, {%8,%9}, {%0,%1,%2,%3};"
               : "+f"(c[0]), "+f"(c[1]), "+f"(c[2]), "+f"(c[3])
               : "r"(a[0]), "r"(a[1]), "r"(a[2]), "r"(a[3]), "r"(b0), "r"(b1));
}

// ---------------------------------------------------------------------------
// Prep: q = W@p folds, per-index score scalars + exps, packed col triples,
// and bf16-split TRANSPOSED feature matrices XhT/XlT.
// ---------------------------------------------------------------------------
__global__ void prep_kernel(const float* __restrict__ nf, const float* __restrict__ ef,
                            const float* __restrict__ Wn, const float* __restrict__ We,
                            const float* __restrict__ pn, const float* __restrict__ pe) {
  __shared__ float sq[256];
  __shared__ float tN[64 * 65];
  __shared__ float tE[64 * 65];
  int t = threadIdx.x;
  int i0 = blockIdx.x * 64;
  {
    int v = t >> 6, d = t & 63;
    const float* W = (v == 1) ? Wn : We;
    const float* p = (v == 0) ? pn : (v == 1) ? (pn + 64) : (v == 2) ? pe : (pe + 64);
    float s = 0.f;
    #pragma unroll
    for (int e = 0; e < 64; e++) s += W[d * 64 + e] * p[e];
    sq[t] = s;
  }
  for (int u = t; u < 1024; u += 256) {
    int r = u >> 4, c = (u & 15) * 4;
    float4 v4 = *(const float4*)(nf + (size_t)(i0 + r) * 64 + c);
    tN[r*65+c] = v4.x; tN[r*65+c+1] = v4.y; tN[r*65+c+2] = v4.z; tN[r*65+c+3] = v4.w;
    float4 e4 = *(const float4*)(ef + (size_t)(i0 + r) * 64 + c);
    tE[r*65+c] = e4.x; tE[r*65+c+1] = e4.y; tE[r*65+c+2] = e4.z; tE[r*65+c+3] = e4.w;
  }
  __syncthreads();
  {
    int v = t & 3, r = t >> 2;
    const float* tl = (v == 1) ? tN : tE;
    const float* q = sq + v * 64;
    float s = 0.f;
    #pragma unroll
    for (int e = 0; e < 64; e++) s += tl[r * 65 + e] * q[e];
    int i = i0 + r;
    float es = expf(s), es2 = expf(0.01f * s);
    if (v == 0)      { g_rA[0][i] = s; g_rEA[0][i] = es; g_rEA2[0][i] = es2; }
    else if (v == 2) { g_rA[1][i] = s; g_rEA[1][i] = es; g_rEA2[1][i] = es2; }
    else if (v == 1) { g_cPack[i]        = make_float4(s, es, es2, 0.f); }
    else             { g_cPack[EDIM + i] = make_float4(s, es, es2, 0.f); }
  }
  for (int u = t; u < 4096; u += 256) {
    int d = u >> 6, ii = u & 63;
    size_t o = (size_t)d * EDIM + i0 + ii;
    float x = tN[ii * 65 + d];
    __nv_bfloat16 h = __float2bfloat16_rn(x);
    g_XhT[0][o] = h;
    g_XlT[0][o] = __float2bfloat16_rn(x - __bfloat162float(h));
    float y = tE[ii * 65 + d];
    __nv_bfloat16 g = __float2bfloat16_rn(y);
    g_XhT[1][o] = g;
    g_XlT[1][o] = __float2bfloat16_rn(y - __bfloat162float(g));
  }
}

// ---- producer X/BV loader (128 threads); adjacency is NOT staged ----
__device__ __forceinline__ void x_load(char* sm, int b, int ch,
    const float4* __restrict__ cPak,
    const __nv_bfloat16* __restrict__ XhT, const __nv_bfloat16* __restrict__ XlT,
    int tp) {
  int k0 = ch * TK;
  char* sXh = sm + OFF_X + (ch & 3) * 16384;
  char* sXl = sXh + 8192;
  #pragma unroll
  for (int u = tp; u < 512; u += 128) {
    int d = u >> 3, o = (u & 7) * 16;
    unsigned off = d * 128 + o;
    unsigned sw = off ^ ((off >> 3) & 0x70);
    cp16(sXh + sw, (const char*)(XhT + (size_t)d * EDIM + k0) + o);
    cp16(sXl + sw, (const char*)(XlT + (size_t)d * EDIM + k0) + o);
  }
  if (tp < 64) cp16(sm + OFF_BV + b * 1024 + tp * 16, (const char*)(cPak + k0 + tp));
}

// ---------------------------------------------------------------------------
// Main: warp-specialized, 8 warps. Warps 4-7 (producers) read adjacency via
// direct LDG (no smem staging), build bf16-split P tiles + Z/cnt, and drive
// cp.async for X/BV. Warps 0-3 (consumers) run
// D += Ph@Xh^T + Ph@Xl^T + Pl@Xh^T via mma.sync (M=32, N=64 per warp).
// ---------------------------------------------------------------------------
__global__ void __launch_bounds__(NTH, 1)
agg_kernel(const int* __restrict__ e2e, const int* __restrict__ n2e,
           const float* __restrict__ Wn, const float* __restrict__ We,
           float* __restrict__ out) {
  extern __shared__ char sm[];
  const int side = blockIdx.z;
  const int*   adjG = side ? e2e : n2e;
  const float* W    = side ? We  : Wn;
  const __nv_bfloat16* XhT = g_XhT[side];
  const __nv_bfloat16* XlT = g_XlT[side];
  const float4* cPak = g_cPack + side * EDIM;
  const int i0 = blockIdx.x * TM;
  const int t  = threadIdx.x;
  const int wid = t >> 5, lane = t & 31;
  const unsigned smb = smem_u32(sm);

  float* sZC = (float*)(sm + OFF_ZC);
  float* sW  = (float*)(sm + OFF_W);

  float acc[2][8][4];
  #pragma unroll
  for (int mt = 0; mt < 2; mt++)
    #pragma unroll
    for (int nb = 0; nb < 8; nb++)
      #pragma unroll
      for (int q = 0; q < 4; q++) acc[mt][nb][q] = 0.f;

  if (t >= 128) {
    // ================= PRODUCERS (warps 4-7) =================
    const int tp = t - 128;
    const int i  = tp;
    const float a_i   = g_rA  [side][i0 + i];
    const float ea_i  = g_rEA [side][i0 + i];
    const float ea2_i = g_rEA2[side][i0 + i];
    const int sx = (i & 7) << 4;
    float zacc = 0.f;
    int   icnt = 0;
    const int* colA = adjG + i0 + i;          // column i, rows k (stride EDIM)

    x_load(sm, 0, 0, cPak, XhT, XlT, tp); cp_commit();
    x_load(sm, 1, 1, cPak, XhT, XlT, tp); cp_commit();

    for (int ch = 0; ch < NCHUNK; ch++) {
      const int b = ch & 1;
      cp_wait1();                       // group for chunk ch complete
      bar_sync(BPROD, 128);             // all producer slices visible
      if (ch >= 2) bar_sync(b ? BFREE1 : BFREE0, NTH);   // P[b] free

      const float4* sBV = (const float4*)(sm + OFF_BV + b * 1024);
      const int* gA = colA + (size_t)ch * (TK * EDIM);
      char* phB = sm + OFF_P + b * 32768 + i * 128;
      char* plB = phB + 16384;
      #pragma unroll 2
      for (int g = 0; g < 8; g++) {
        int mg[8];
        #pragma unroll
        for (int j = 0; j < 8; j++) mg[j] = gA[(g * 8 + j) * EDIM];  // direct LDG
        unsigned ph4[4], pl4[4];
        #pragma unroll
        for (int jj = 0; jj < 4; jj++) {
          int k = g * 8 + jj * 2;
          float4 b0 = sBV[k], b1 = sBV[k + 1];
          float s0 = (a_i + b0.x >= 0.f) ? ea_i * b0.y : ea2_i * b0.z;
          float s1 = (a_i + b1.x >= 0.f) ? ea_i * b1.y : ea2_i * b1.z;
          bool p0 = mg[2 * jj] > 0, p1 = mg[2 * jj + 1] > 0;
          float w0 = p0 ? s0 : 0.f;
          float w1 = p1 ? s1 : 0.f;
          zacc += w0; zacc += w1;
          icnt += p0 ? 1 : 0;
          icnt += p1 ? 1 : 0;
          unsigned ph;
          asm("cvt.rn.bf16x2.f32 %0, %1, %2;" : "=r"(ph) : "f"(w1), "f"(w0));
          float h0 = __uint_as_float(ph << 16);
          float h1 = __uint_as_float(ph & 0xffff0000u);
          unsigned pl;
          asm("cvt.rn.bf16x2.f32 %0, %1, %2;" : "=r"(pl) : "f"(w1 - h1), "f"(w0 - h0));
          ph4[jj] = ph; pl4[jj] = pl;
        }
        int off = (g * 16) ^ sx;
        *(uint4*)(phB + off) = make_uint4(ph4[0], ph4[1], ph4[2], ph4[3]);
        *(uint4*)(plB + off) = make_uint4(pl4[0], pl4[1], pl4[2], pl4[3]);
      }
      bar_arrive(b ? BFULL1 : BFULL0, NTH);
      bar_sync(BPROD, 128);             // BV[b] fully consumed by producers
      if (ch + 2 < NCHUNK)
        x_load(sm, b, ch + 2, cPak, XhT, XlT, tp);
      cp_commit();                      // always one group per iteration
    }
    sZC[i]       = zacc;
    sZC[128 + i] = (float)icnt;
  } else {
    // ================= CONSUMERS (warps 0-3) =================
    for (int u = t; u < 1024; u += 128)
      ((float4*)sW)[u] = ((const float4*)W)[u];

    const unsigned mBase = (unsigned)(wid * 32 + (lane & 15)) * 128;
    const unsigned aXor  = (lane & 7) << 4;
    const unsigned aCol  = (lane >> 4) << 4;
    unsigned dBase[4], dXor[4];
    {
      int dRow = ((lane >> 4) << 3) + (lane & 7);
      #pragma unroll
      for (int np = 0; np < 4; np++) {
        int d = np * 16 + dRow;
        dBase[np] = (unsigned)d * 128;
        dXor[np]  = (d & 7) << 4;
      }
    }
    const unsigned bCol = ((lane >> 3) & 1) << 4;

    for (int ch = 0; ch < NCHUNK; ch++) {
      const int b = ch & 1;
      bar_sync(b ? BFULL1 : BFULL0, NTH);
      const unsigned pPh = smb + OFF_P + b * 32768;
      const unsigned pPl = pPh + 16384;
      const unsigned pXh = smb + OFF_X + (ch & 3) * 16384;
      const unsigned pXl = pXh + 8192;
      #pragma unroll
      for (int ks = 0; ks < 4; ks++) {
        unsigned ah0[4], ah1[4], al0[4], al1[4];
        unsigned aOff = ((unsigned)(ks * 32) + aCol) ^ aXor;
        ldsm4(ah0[0], ah0[1], ah0[2], ah0[3], pPh + mBase + aOff);
        ldsm4(ah1[0], ah1[1], ah1[2], ah1[3], pPh + mBase + 2048 + aOff);
        ldsm4(al0[0], al0[1], al0[2], al0[3], pPl + mBase + aOff);
        ldsm4(al1[0], al1[1], al1[2], al1[3], pPl + mBase + 2048 + aOff);
        #pragma unroll
        for (int np = 0; np < 4; np++) {
          unsigned bh[4], bl[4];
          unsigned bOff = ((unsigned)(ks * 32) + bCol) ^ dXor[np];
          ldsm4(bh[0], bh[1], bh[2], bh[3], pXh + dBase[np] + bOff);
          ldsm4(bl[0], bl[1], bl[2], bl[3], pXl + dBase[np] + bOff);
          mma16816(acc[0][2*np],   ah0, bh[0], bh[1]);
          mma16816(acc[0][2*np+1], ah0, bh[2], bh[3]);
          mma16816(acc[1][2*np],   ah1, bh[0], bh[1]);
          mma16816(acc[1][2*np+1], ah1, bh[2], bh[3]);
          mma16816(acc[0][2*np],   ah0, bl[0], bl[1]);
          mma16816(acc[0][2*np+1], ah0, bl[2], bl[3]);
          mma16816(acc[1][2*np],   ah1, bl[0], bl[1]);
          mma16816(acc[1][2*np+1], ah1, bl[2], bl[3]);
          mma16816(acc[0][2*np],   al0, bh[0], bh[1]);
          mma16816(acc[0][2*np+1], al0, bh[2], bh[3]);
          mma16816(acc[1][2*np],   al1, bh[0], bh[1]);
          mma16816(acc[1][2*np+1], al1, bh[2], bh[3]);
        }
      }
      bar_arrive(b ? BFREE1 : BFREE0, NTH);
    }
  }

  __syncthreads();   // producers wrote sZC; consumers hold acc; P region dead

  // ---- epilogue: consumers scatter normalized means into sM ----
  float* sM = (float*)(sm + OFF_M);
  if (t < 128) {
    #pragma unroll
    for (int mt = 0; mt < 2; mt++) {
      int base = wid * 32 + mt * 16 + (lane >> 2);
      int r0e = base, r1e = base + 8;
      float inv0 = 1.f / (sZC[r0e] * sZC[128 + r0e]);
      float inv1 = 1.f / (sZC[r1e] * sZC[128 + r1e]);
      #pragma unroll
      for (int nb = 0; nb < 8; nb++) {
        int c = nb * 8 + (lane & 3) * 2;
        sM[r0e * MSTRIDE + c]     = acc[mt][nb][0] * inv0;
        sM[r0e * MSTRIDE + c + 1] = acc[mt][nb][1] * inv0;
        sM[r1e * MSTRIDE + c]     = acc[mt][nb][2] * inv1;
        sM[r1e * MSTRIDE + c + 1] = acc[mt][nb][3] * inv1;
      }
    }
  }
  __syncthreads();

  // ---- projection through W + leaky + store (all 256 threads) ----
  const int tx = t & 7, ty = t >> 3;
  const int r0 = ty * 4, c0 = tx * 8;
  float o[4][8] = {};
  #pragma unroll 8
  for (int k = 0; k < 64; k++) {
    float mr[4];
    #pragma unroll
    for (int rr = 0; rr < 4; rr++) mr[rr] = sM[(r0 + rr) * MSTRIDE + k];
    float4 wa = *(const float4*)(sW + k * 64 + c0);
    float4 wb = *(const float4*)(sW + k * 64 + c0 + 4);
    float wv[8] = {wa.x, wa.y, wa.z, wa.w, wb.x, wb.y, wb.z, wb.w};
    #pragma unroll
    for (int rr = 0; rr < 4; rr++)
      #pragma unroll
      for (int cc = 0; cc < 8; cc++)
        o[rr][cc] = fmaf(mr[rr], wv[cc], o[rr][cc]);
  }
  #pragma unroll
  for (int rr = 0; rr < 4; rr++) {
    float v[8];
    #pragma unroll
    for (int cc = 0; cc < 8; cc++) {
      float x = o[rr][cc];
      v[cc] = (x >= 0.f) ? x : 0.01f * x;
    }
    float* op = out + (size_t)(i0 + r0 + rr) * 128 + side * 64 + c0;
    *(float4*)(op)     = make_float4(v[0], v[1], v[2], v[3]);
    *(float4*)(op + 4) = make_float4(v[4], v[5], v[6], v[7]);
  }
}

// ---------------------------------------------------------------------------
extern "C" void kernel_launch(void* const* d_in, const int* in_sizes, int n_in,
                              void* d_out, int out_size) {
  const float* nf  = (const float*)d_in[0];
  const float* ef  = (const float*)d_in[1];
  const int*   e2e = (const int*)  d_in[2];
  const int*   n2e = (const int*)  d_in[3];
  const float* Wn  = (const float*)d_in[4];
  const float* We  = (const float*)d_in[5];
  const float* pn  = (const float*)d_in[6];
  const float* pe  = (const float*)d_in[7];
  float* out = (float*)d_out;

  cudaFuncSetAttribute(agg_kernel, cudaFuncAttributeMaxDynamicSharedMemorySize, SMEM_BYTES);

  prep_kernel<<<EDIM / 64, 256>>>(nf, ef, Wn, We, pn, pe);
  dim3 grid(EDIM / TM, 1, 2);
  agg_kernel<<<grid, NTH, SMEM_BYTES>>>(e2e, n2e, Wn, We, out);
}

// round 12
// speedup vs baseline: 2.1775x; 2.1775x over previous
#include <cuda_runtime.h>
#include <cuda_bf16.h>
#include <math.h>

#define EDIM 8192      // N == E == 8192
#define TM   256       // rows per CTA
#define TK   32        // K-chunk
#define NTH  256
#define NCH_HALF 128   // chunks per CTA (half of 8192/32)

// ---- shared memory layout (bytes) ----
#define OFF_A    0          // 2 x 32 KB adjacency staging [32 k][256 i] int32
#define OFF_P    65536      // 2 x (Ph 16KB + Pl 16KB) rows=64B, SW64
#define OFF_X    131072     // 4 x 8 KB (Xh 4KB + Xl 4KB) [64 d][32 k] bf16, SW64
#define OFF_BV   163840     // 2 x 512 B packed col triples float4[32]
#define OFF_W2   164864     // (unused in agg)
#define SMEM_BYTES 183296

// named barrier ids
#define BFULL0 1
#define BFULL1 2
#define BFREE0 3
#define BFREE1 4
#define BPROD  5

// ---- device scratch ----
__device__ __align__(16) float g_rA  [2][EDIM];
__device__ __align__(16) float g_rEA [2][EDIM];
__device__ __align__(16) float g_rEA2[2][EDIM];
__device__ __align__(16) float4 g_cPack[2 * EDIM];          // {b, eb, eb2, 0}
__device__ __align__(16) __nv_bfloat16 g_XhT[2][64 * EDIM]; // X^T hi split [d][k]
__device__ __align__(16) __nv_bfloat16 g_XlT[2][64 * EDIM]; // X^T lo split
__device__ __align__(16) float g_part[4][EDIM * 64];        // [side*2+kh][i][d]
__device__ __align__(16) float g_z [4][EDIM];
__device__ __align__(16) float g_c [4][EDIM];

// ---- PTX helpers ----
__device__ __forceinline__ unsigned smem_u32(const void* p) {
  unsigned a;
  asm("{ .reg .u64 t; cvta.to.shared.u64 t, %1; cvt.u32.u64 %0, t; }" : "=r"(a) : "l"(p));
  return a;
}
__device__ __forceinline__ void cp16(void* dst, const void* src) {
  unsigned sa = smem_u32(dst);
  asm volatile("cp.async.cg.shared.global [%0], [%1], 16;" :: "r"(sa), "l"(src) : "memory");
}
__device__ __forceinline__ void cp_commit() { asm volatile("cp.async.commit_group;" ::: "memory"); }
__device__ __forceinline__ void cp_wait1()  { asm volatile("cp.async.wait_group 1;" ::: "memory"); }

__device__ __forceinline__ void bar_sync(int id, int cnt) {
  asm volatile("bar.sync %0, %1;" :: "r"(id), "r"(cnt) : "memory");
}
__device__ __forceinline__ void bar_arrive(int id, int cnt) {
  asm volatile("bar.arrive %0, %1;" :: "r"(id), "r"(cnt) : "memory");
}

__device__ __forceinline__ void ldsm4(unsigned& r0, unsigned& r1, unsigned& r2, unsigned& r3,
                                      unsigned addr) {
  asm volatile("ldmatrix.sync.aligned.m8n8.x4.shared.b16 {%0,%1,%2,%3}, [%4];"
               : "=r"(r0), "=r"(r1), "=r"(r2), "=r"(r3) : "r"(addr));
}
__device__ __forceinline__ void mma16816(float* c, const unsigned* a, unsigned b0, unsigned b1) {
  asm volatile("mma.sync.aligned.m16n8k16.row.col.f32.bf16.bf16.f32 "
               "{%0,%1,%2,%3}, {%4,%5,%6,%7}, {%8,%9}, {%0,%1,%2,%3};"
               : "+f"(c[0]), "+f"(c[1]), "+f"(c[2]), "+f"(c[3])
               : "r"(a[0]), "r"(a[1]), "r"(a[2]), "r"(a[3]), "r"(b0), "r"(b1));
}

// ---------------------------------------------------------------------------
// Prep (unchanged): scalars + exps, col triples, bf16-split X^T.
// ---------------------------------------------------------------------------
__global__ void prep_kernel(const float* __restrict__ nf, const float* __restrict__ ef,
                            const float* __restrict__ Wn, const float* __restrict__ We,
                            const float* __restrict__ pn, const float* __restrict__ pe) {
  __shared__ float sq[256];
  __shared__ float tN[64 * 65];
  __shared__ float tE[64 * 65];
  int t = threadIdx.x;
  int i0 = blockIdx.x * 64;
  {
    int v = t >> 6, d = t & 63;
    const float* W = (v == 1) ? Wn : We;
    const float* p = (v == 0) ? pn : (v == 1) ? (pn + 64) : (v == 2) ? pe : (pe + 64);
    float s = 0.f;
    #pragma unroll
    for (int e = 0; e < 64; e++) s += W[d * 64 + e] * p[e];
    sq[t] = s;
  }
  for (int u = t; u < 1024; u += 256) {
    int r = u >> 4, c = (u & 15) * 4;
    float4 v4 = *(const float4*)(nf + (size_t)(i0 + r) * 64 + c);
    tN[r*65+c] = v4.x; tN[r*65+c+1] = v4.y; tN[r*65+c+2] = v4.z; tN[r*65+c+3] = v4.w;
    float4 e4 = *(const float4*)(ef + (size_t)(i0 + r) * 64 + c);
    tE[r*65+c] = e4.x; tE[r*65+c+1] = e4.y; tE[r*65+c+2] = e4.z; tE[r*65+c+3] = e4.w;
  }
  __syncthreads();
  {
    int v = t & 3, r = t >> 2;
    const float* tl = (v == 1) ? tN : tE;
    const float* q = sq + v * 64;
    float s = 0.f;
    #pragma unroll
    for (int e = 0; e < 64; e++) s += tl[r * 65 + e] * q[e];
    int i = i0 + r;
    float es = expf(s), es2 = expf(0.01f * s);
    if (v == 0)      { g_rA[0][i] = s; g_rEA[0][i] = es; g_rEA2[0][i] = es2; }
    else if (v == 2) { g_rA[1][i] = s; g_rEA[1][i] = es; g_rEA2[1][i] = es2; }
    else if (v == 1) { g_cPack[i]        = make_float4(s, es, es2, 0.f); }
    else             { g_cPack[EDIM + i] = make_float4(s, es, es2, 0.f); }
  }
  for (int u = t; u < 4096; u += 256) {
    int d = u >> 6, ii = u & 63;
    size_t o = (size_t)d * EDIM + i0 + ii;
    float x = tN[ii * 65 + d];
    __nv_bfloat16 h = __float2bfloat16_rn(x);
    g_XhT[0][o] = h;
    g_XlT[0][o] = __float2bfloat16_rn(x - __bfloat162float(h));
    float y = tE[ii * 65 + d];
    __nv_bfloat16 g = __float2bfloat16_rn(y);
    g_XhT[1][o] = g;
    g_XlT[1][o] = __float2bfloat16_rn(y - __bfloat162float(g));
  }
}

// ---- producer loaders (128 threads) ----
__device__ __forceinline__ void a_load(char* sm, int b, int ch,
    const int* __restrict__ adjG, int i0g, int tp) {
  char* sA = sm + OFF_A + b * 32768;
  const char* adjB = (const char*)adjG;
  int k0 = ch * TK;
  #pragma unroll
  for (int u = tp; u < 2048; u += 128) {
    int kk = u >> 6, o = u & 63;
    cp16(sA + kk * 1024 + o * 16,
         adjB + (((size_t)(k0 + kk) * EDIM + i0g) << 2) + (size_t)o * 16);
  }
}
__device__ __forceinline__ void x_load(char* sm, int b, int ch,
    const float4* __restrict__ cPak,
    const __nv_bfloat16* __restrict__ XhT, const __nv_bfloat16* __restrict__ XlT,
    int tp) {
  int k0 = ch * TK;
  char* sXh = sm + OFF_X + (ch & 3) * 8192;
  char* sXl = sXh + 4096;
  #pragma unroll
  for (int u = tp; u < 256; u += 128) {
    int d = u >> 2, o = (u & 3) * 16;
    unsigned sw = (d * 64 + o) ^ ((d & 6) << 3);       // SW64
    cp16(sXh + sw, (const char*)(XhT + (size_t)d * EDIM + k0) + o);
    cp16(sXl + sw, (const char*)(XlT + (size_t)d * EDIM + k0) + o);
  }
  if (tp < 32) cp16(sm + OFF_BV + b * 512 + tp * 16, (const char*)(cPak + k0 + tp));
}

// ---------------------------------------------------------------------------
// Agg: TM=256, K=32 chunks, K-split. grid (32, 2 kh, 2 side).
// Producers (warps 4-7): 2 rows/thread, bf16-split P (SW64) + Z/cnt.
// Consumers (warps 0-3): M=64 x N=64 per warp, 3-product bf16 mma.
// Writes raw partial accumulators + Z/cnt to global scratch.
// ---------------------------------------------------------------------------
__global__ void __launch_bounds__(NTH, 1)
agg_kernel(const int* __restrict__ e2e, const int* __restrict__ n2e) {
  extern __shared__ char sm[];
  const int side = blockIdx.z, kh = blockIdx.y;
  const int slot = side * 2 + kh;
  const int*   adjG = side ? e2e : n2e;
  const __nv_bfloat16* XhT = g_XhT[side];
  const __nv_bfloat16* XlT = g_XlT[side];
  const float4* cPak = g_cPack + side * EDIM;
  const int i0g = blockIdx.x * TM;
  const int t  = threadIdx.x;
  const int wid = t >> 5, lane = t & 31;
  const unsigned smb = smem_u32(sm);
  const int ch0 = kh * NCH_HALF;

  if (t >= 128) {
    // ================= PRODUCERS (warps 4-7), 2 rows each =================
    const int tp = t - 128;
    const int iA = tp, iB = tp + 128;
    const float aA   = g_rA  [side][i0g + iA];
    const float eaA  = g_rEA [side][i0g + iA];
    const float ea2A = g_rEA2[side][i0g + iA];
    const float aB   = g_rA  [side][i0g + iB];
    const float eaB  = g_rEA [side][i0g + iB];
    const float ea2B = g_rEA2[side][i0g + iB];
    const int sxA = (iA & 6) << 3, sxB = (iB & 6) << 3;
    float zA = 0.f, zB = 0.f;
    int cA = 0, cB = 0;

    a_load(sm, 0, ch0 + 0, adjG, i0g, tp);
    x_load(sm, 0, ch0 + 0, cPak, XhT, XlT, tp); cp_commit();
    a_load(sm, 1, ch0 + 1, adjG, i0g, tp);
    x_load(sm, 1, ch0 + 1, cPak, XhT, XlT, tp); cp_commit();

    for (int cc = 0; cc < NCH_HALF; cc++) {
      const int b = cc & 1;
      cp_wait1();
      bar_sync(BPROD, 128);
      if (cc >= 2) bar_sync(b ? BFREE1 : BFREE0, NTH);

      const int*    sAdj = (const int*)   (sm + OFF_A  + b * 32768);
      const float4* sBV  = (const float4*)(sm + OFF_BV + b * 512);
      char* phA = sm + OFF_P + b * 32768 + iA * 64;
      char* plA = phA + 16384;
      char* phB = sm + OFF_P + b * 32768 + iB * 64;
      char* plB = phB + 16384;
      #pragma unroll
      for (int g = 0; g < 4; g++) {
        unsigned pha[4], pla[4], phb[4], plb[4];
        #pragma unroll
        for (int jj = 0; jj < 4; jj++) {
          int k = g * 8 + jj * 2;
          int m0a = sAdj[k * TM + iA],       m1a = sAdj[(k + 1) * TM + iA];
          int m0b = sAdj[k * TM + iB],       m1b = sAdj[(k + 1) * TM + iB];
          float4 b0 = sBV[k], b1 = sBV[k + 1];
          float s0A = (aA + b0.x >= 0.f) ? eaA * b0.y : ea2A * b0.z;
          float s1A = (aA + b1.x >= 0.f) ? eaA * b1.y : ea2A * b1.z;
          float s0B = (aB + b0.x >= 0.f) ? eaB * b0.y : ea2B * b0.z;
          float s1B = (aB + b1.x >= 0.f) ? eaB * b1.y : ea2B * b1.z;
          float w0a = (m0a > 0) ? s0A : 0.f, w1a = (m1a > 0) ? s1A : 0.f;
          float w0b = (m0b > 0) ? s0B : 0.f, w1b = (m1b > 0) ? s1B : 0.f;
          zA += w0a + w1a;  zB += w0b + w1b;
          cA += (m0a > 0) + (m1a > 0);
          cB += (m0b > 0) + (m1b > 0);
          unsigned ph, pl;
          asm("cvt.rn.bf16x2.f32 %0, %1, %2;" : "=r"(ph) : "f"(w1a), "f"(w0a));
          {
            float h0 = __uint_as_float(ph << 16), h1 = __uint_as_float(ph & 0xffff0000u);
            asm("cvt.rn.bf16x2.f32 %0, %1, %2;" : "=r"(pl) : "f"(w1a - h1), "f"(w0a - h0));
          }
          pha[jj] = ph; pla[jj] = pl;
          asm("cvt.rn.bf16x2.f32 %0, %1, %2;" : "=r"(ph) : "f"(w1b), "f"(w0b));
          {
            float h0 = __uint_as_float(ph << 16), h1 = __uint_as_float(ph & 0xffff0000u);
            asm("cvt.rn.bf16x2.f32 %0, %1, %2;" : "=r"(pl) : "f"(w1b - h1), "f"(w0b - h0));
          }
          phb[jj] = ph; plb[jj] = pl;
        }
        int offA = (g * 16) ^ sxA;
        int offB = (g * 16) ^ sxB;
        *(uint4*)(phA + offA) = make_uint4(pha[0], pha[1], pha[2], pha[3]);
        *(uint4*)(plA + offA) = make_uint4(pla[0], pla[1], pla[2], pla[3]);
        *(uint4*)(phB + offB) = make_uint4(phb[0], phb[1], phb[2], phb[3]);
        *(uint4*)(plB + offB) = make_uint4(plb[0], plb[1], plb[2], plb[3]);
      }
      bar_arrive(b ? BFULL1 : BFULL0, NTH);
      bar_sync(BPROD, 128);
      if (cc + 2 < NCH_HALF) {
        a_load(sm, b, ch0 + cc + 2, adjG, i0g, tp);
        x_load(sm, b, ch0 + cc + 2, cPak, XhT, XlT, tp);
      }
      cp_commit();
    }
    g_z[slot][i0g + iA] = zA;  g_c[slot][i0g + iA] = (float)cA;
    g_z[slot][i0g + iB] = zB;  g_c[slot][i0g + iB] = (float)cB;
  } else {
    // ================= CONSUMERS (warps 0-3): M=64, N=64 each ============
    const int m0 = wid * 64;
    const unsigned aCol = (lane >> 4) << 4;
    const int arL = lane & 15;
    unsigned dRow = ((lane >> 4) << 3) + (lane & 7);
    const unsigned bCol = ((lane >> 3) & 1) << 4;

    float acc[4][8][4];
    #pragma unroll
    for (int mt = 0; mt < 4; mt++)
      #pragma unroll
      for (int nb = 0; nb < 8; nb++)
        #pragma unroll
        for (int q = 0; q < 4; q++) acc[mt][nb][q] = 0.f;

    for (int cc = 0; cc < NCH_HALF; cc++) {
      const int b = cc & 1;
      bar_sync(b ? BFULL1 : BFULL0, NTH);
      const unsigned pPh = smb + OFF_P + b * 32768;
      const unsigned pPl = pPh + 16384;
      const unsigned pXh = smb + OFF_X + ((ch0 + cc) & 3) * 8192;
      const unsigned pXl = pXh + 4096;
      #pragma unroll
      for (int ks = 0; ks < 2; ks++) {
        unsigned ah[4][4], al[4][4];
        #pragma unroll
        for (int mt = 0; mt < 4; mt++) {
          int ar = m0 + mt * 16 + arL;
          unsigned aOff = (unsigned)(ar * 64) + (((unsigned)(ks * 32) + aCol) ^ ((ar & 6) << 3));
          ldsm4(ah[mt][0], ah[mt][1], ah[mt][2], ah[mt][3], pPh + aOff);
          ldsm4(al[mt][0], al[mt][1], al[mt][2], al[mt][3], pPl + aOff);
        }
        #pragma unroll
        for (int np = 0; np < 4; np++) {
          int d = np * 16 + dRow;
          unsigned bOff = (unsigned)(d * 64) + (((unsigned)(ks * 32) + bCol) ^ ((d & 6) << 3));
          unsigned bh[4], bl[4];
          ldsm4(bh[0], bh[1], bh[2], bh[3], pXh + bOff);
          ldsm4(bl[0], bl[1], bl[2], bl[3], pXl + bOff);
          #pragma unroll
          for (int mt = 0; mt < 4; mt++) {
            mma16816(acc[mt][np*2],   ah[mt], bh[0], bh[1]);
            mma16816(acc[mt][np*2+1], ah[mt], bh[2], bh[3]);
            mma16816(acc[mt][np*2],   ah[mt], bl[0], bl[1]);
            mma16816(acc[mt][np*2+1], ah[mt], bl[2], bl[3]);
            mma16816(acc[mt][np*2],   al[mt], bh[0], bh[1]);
            mma16816(acc[mt][np*2+1], al[mt], bh[2], bh[3]);
          }
        }
      }
      bar_arrive(b ? BFREE1 : BFREE0, NTH);
    }

    // ---- store raw partial accumulators to global scratch ----
    float* base = g_part[slot];
    #pragma unroll
    for (int mt = 0; mt < 4; mt++) {
      int r0e = m0 + mt * 16 + (lane >> 2);
      int r1e = r0e + 8;
      float* p0 = base + ((size_t)(i0g + r0e) << 6);
      float* p1 = base + ((size_t)(i0g + r1e) << 6);
      #pragma unroll
      for (int nb = 0; nb < 8; nb++) {
        int c = nb * 8 + (lane & 3) * 2;
        *(float2*)(p0 + c) = make_float2(acc[mt][nb][0], acc[mt][nb][1]);
        *(float2*)(p1 + c) = make_float2(acc[mt][nb][2], acc[mt][nb][3]);
      }
    }
  }
}

// ---------------------------------------------------------------------------
// Combine: sum K-halves, normalize by Z*cnt, project through W, leaky, store.
// grid (64, 2 side); block handles 128 rows.
// ---------------------------------------------------------------------------
#define MSTRIDE 65
#define SMEM2 (128 * MSTRIDE * 4 + 16384 + 1024)
__global__ void __launch_bounds__(256, 1)
combine_kernel(const float* __restrict__ Wn, const float* __restrict__ We,
               float* __restrict__ out) {
  extern __shared__ char smc[];
  float* sM = (float*)smc;                       // 128 x 65
  float* sW = (float*)(smc + 128 * MSTRIDE * 4); // 16 KB
  float* sI = sW + 4096;                         // 128 inv factors
  const int side = blockIdx.y;
  const float* W = side ? We : Wn;
  const int i0c = blockIdx.x * 128;
  const int t = threadIdx.x;

  if (t < 128) {
    int gi = i0c + t;
    float z = g_z[side*2][gi] + g_z[side*2+1][gi];
    float c = g_c[side*2][gi] + g_c[side*2+1][gi];
    sI[t] = 1.f / (z * c);
  }
  for (int u = t; u < 1024; u += 256)
    ((float4*)sW)[u] = ((const float4*)W)[u];
  __syncthreads();

  for (int u = t; u < 2048; u += 256) {
    int r = u >> 4, c = (u & 15) * 4;
    size_t go = ((size_t)(i0c + r) << 6) + c;
    float4 p0 = *(const float4*)(g_part[side*2]     + go);
    float4 p1 = *(const float4*)(g_part[side*2 + 1] + go);
    float inv = sI[r];
    sM[r*MSTRIDE + c]     = (p0.x + p1.x) * inv;
    sM[r*MSTRIDE + c + 1] = (p0.y + p1.y) * inv;
    sM[r*MSTRIDE + c + 2] = (p0.z + p1.z) * inv;
    sM[r*MSTRIDE + c + 3] = (p0.w + p1.w) * inv;
  }
  __syncthreads();

  const int tx = t & 7, ty = t >> 3;
  const int r0 = ty * 4, c0 = tx * 8;
  float o[4][8] = {};
  #pragma unroll 8
  for (int k = 0; k < 64; k++) {
    float mr[4];
    #pragma unroll
    for (int rr = 0; rr < 4; rr++) mr[rr] = sM[(r0 + rr) * MSTRIDE + k];
    float4 wa = *(const float4*)(sW + k * 64 + c0);
    float4 wb = *(const float4*)(sW + k * 64 + c0 + 4);
    float wv[8] = {wa.x, wa.y, wa.z, wa.w, wb.x, wb.y, wb.z, wb.w};
    #pragma unroll
    for (int rr = 0; rr < 4; rr++)
      #pragma unroll
      for (int cc = 0; cc < 8; cc++)
        o[rr][cc] = fmaf(mr[rr], wv[cc], o[rr][cc]);
  }
  #pragma unroll
  for (int rr = 0; rr < 4; rr++) {
    float v[8];
    #pragma unroll
    for (int cc = 0; cc < 8; cc++) {
      float x = o[rr][cc];
      v[cc] = (x >= 0.f) ? x : 0.01f * x;
    }
    float* op = out + (size_t)(i0c + r0 + rr) * 128 + side * 64 + c0;
    *(float4*)(op)     = make_float4(v[0], v[1], v[2], v[3]);
    *(float4*)(op + 4) = make_float4(v[4], v[5], v[6], v[7]);
  }
}

// ---------------------------------------------------------------------------
extern "C" void kernel_launch(void* const* d_in, const int* in_sizes, int n_in,
                              void* d_out, int out_size) {
  const float* nf  = (const float*)d_in[0];
  const float* ef  = (const float*)d_in[1];
  const int*   e2e = (const int*)  d_in[2];
  const int*   n2e = (const int*)  d_in[3];
  const float* Wn  = (const float*)d_in[4];
  const float* We  = (const float*)d_in[5];
  const float* pn  = (const float*)d_in[6];
  const float* pe  = (const float*)d_in[7];
  float* out = (float*)d_out;

  cudaFuncSetAttribute(agg_kernel, cudaFuncAttributeMaxDynamicSharedMemorySize, SMEM_BYTES);
  cudaFuncSetAttribute(combine_kernel, cudaFuncAttributeMaxDynamicSharedMemorySize, SMEM2);

  prep_kernel<<<EDIM / 64, 256>>>(nf, ef, Wn, We, pn, pe);
  dim3 grid(EDIM / TM, 2, 2);
  agg_kernel<<<grid, NTH, SMEM_BYTES>>>(e2e, n2e);
  dim3 grid2(EDIM / 128, 2);
  combine_kernel<<<grid2, 256, SMEM2>>>(Wn, We, out);
}